// round 4
// baseline (speedup 1.0000x reference)
#include <cuda_runtime.h>
#include <cuda_bf16.h>
#include <cstdint>

// Problem constants
#define NC   19
#define HW   (512 * 512)
#define NB   8
#define GX   18                 // blocks per batch image -> 144 blocks total (one wave on 148+ SMs)
#define T    128                // threads per block
#define NBINS (NC * NC + NC)    // 361 S-bins + 19 count-bins = 380
#define CHUNK 14564             // ceil(HW/GX), even (float2/int2/ulonglong2 alignment holds)

// Per-block partial results: [block][bin]; written without atomics -> deterministic.
__device__ float g_part[GX * NB][NBINS];
// Label dtype flag: 1 = int64 labels, 0 = int32 labels.
__device__ int g_is64;

// ---------------------------------------------------------------------------
// Detect whether labels are int64 (odd 32-bit words all zero) or int32.
// Reads only 512 bytes -> safe for either layout.
__global__ void detect_kernel(const int* __restrict__ lab32) {
    int acc = 0;
#pragma unroll
    for (int j = 0; j < 64; j++) acc |= lab32[2 * j + 1];
    g_is64 = (acc == 0) ? 1 : 0;
}

// ---------------------------------------------------------------------------
// Accumulate one pair of pixels into this thread's private shared columns.
// acc = s + tid;  bin layout: (i*NC + k)*T + tid ; counts at (NC*NC + k)*T + tid.
// Conflict-free: (bin*128 + tid) % 32 == tid % 32 for every bin.
__device__ __forceinline__ void accum_pair(float* acc, const float2 v[NC], int k0, int k1) {
    float* a0 = acc + (unsigned)k0 * T;
    float* a1 = acc + (unsigned)k1 * T;
#pragma unroll
    for (int i = 0; i < NC; i++) {
        a0[i * NC * T] += v[i].x;
        a1[i * NC * T] += v[i].y;
    }
    acc[(NC * NC + k0) * T] += 1.0f;
    acc[(NC * NC + k1) * T] += 1.0f;
}

template <bool IS64>
__device__ __forceinline__ void load_pair(const void* __restrict__ lab, long long labbase,
                                          const float* __restrict__ segp, int p,
                                          float2 v[NC], int& k0, int& k1) {
    if (IS64) {
        ulonglong2 L = __ldcs((const ulonglong2*)((const long long*)lab + labbase + p));
        k0 = (int)L.x;
        k1 = (int)L.y;
    } else {
        int2 L = __ldcs((const int2*)((const int*)lab + labbase + p));
        k0 = L.x;
        k1 = L.y;
    }
#pragma unroll
    for (int i = 0; i < NC; i++)
        v[i] = __ldcs((const float2*)(segp + (size_t)i * HW + p));
}

template <bool IS64>
__device__ __forceinline__ void run_accum(const float* __restrict__ seg,
                                          const void* __restrict__ lab,
                                          float* s) {
    const int tid = threadIdx.x;
    const int bx = blockIdx.x;
    const int b  = blockIdx.y;

    // Zero this block's shared accumulators.
    for (int i = tid; i < NBINS * T; i += T) s[i] = 0.0f;
    __syncthreads();

    const int start = bx * CHUNK;
    const int end   = min(start + CHUNK, HW);
    const long long labbase = (long long)b * HW;
    const float* segp = seg + (size_t)b * NC * HW;
    float* acc = s + tid;

    const int step = 2 * T;           // pixels per block per phase
    int p = start + 2 * tid;          // this thread's first pixel pair

    float2 vA[NC], vB[NC];
    int a0 = 0, a1 = 0, b0 = 0, b1 = 0;

    // Software double-buffer: keep one phase of 19 LDG.64 in flight while
    // accumulating the previous phase -> ~38 loads (~4.9 KB) in flight/thread.
    bool va = (p < end);
    if (va) load_pair<IS64>(lab, labbase, segp, p, vA, a0, a1);
    while (va) {
        int pB = p + step;
        bool vb = (pB < end);
        if (vb) load_pair<IS64>(lab, labbase, segp, pB, vB, b0, b1);  // prefetch B
        accum_pair(acc, vA, a0, a1);                                  // consume A
        if (!vb) break;
        int pA = pB + step;
        va = (pA < end);
        if (va) load_pair<IS64>(lab, labbase, segp, pA, vA, a0, a1);  // prefetch A
        accum_pair(acc, vB, b0, b1);                                  // consume B
        p = pA;
    }
    __syncthreads();

    // Reduce the 128 thread-columns per bin; rotate start index to stay conflict-free.
    float* outrow = g_part[b * GX + bx];
    for (int bin = tid; bin < NBINS; bin += T) {
        float sum = 0.0f;
        const float* col = s + bin * T;
#pragma unroll 8
        for (int t = 0; t < T; t++) sum += col[(t + tid) & (T - 1)];
        outrow[bin] = sum;
    }
}

__global__ __launch_bounds__(T, 1) void accum_kernel(const float* __restrict__ seg,
                                                     const void* __restrict__ lab) {
    extern __shared__ float s[];     // [NBINS][T] floats = 194,560 B (< 227 KB sm_103a cap)
    if (g_is64) run_accum<true>(seg, lab, s);
    else        run_accum<false>(seg, lab, s);
}

// ---------------------------------------------------------------------------
// Combine partials, compute the log-sum loss. One block, 384 threads.
__global__ __launch_bounds__(384) void finalize_kernel(float* __restrict__ out) {
    __shared__ float sS[NB][NBINS];
    __shared__ double ws[12];
    const int t = threadIdx.x;

    for (int idx = t; idx < NB * NBINS; idx += 384) {
        int b = idx / NBINS, bin = idx % NBINS;
        float s = 0.0f;
#pragma unroll
        for (int g = 0; g < GX; g++) s += g_part[b * GX + g][bin];
        sS[b][bin] = s;
    }
    __syncthreads();

    double local = 0.0;
    if (t < NC * NC) {
        const int i = t / NC, k = t % NC;
#pragma unroll
        for (int b = 0; b < NB; b++) {
            float cnt_i = sS[b][NC * NC + i];
            float cnt_k = sS[b][NC * NC + k];
            float Sii   = sS[b][i * NC + i];
            float Sik   = sS[b][i * NC + k];
            double alpha = (cnt_i > 0.0f) ? (double)Sii / (double)cnt_i : 0.0;
            double beta  = (cnt_k > 0.0f) ? 1.0 - (double)Sik / (double)cnt_k : 0.0;
            local += log(0.5 * (alpha + beta + 2.220446049250313e-16));
        }
    }
#pragma unroll
    for (int o = 16; o; o >>= 1)
        local += __shfl_down_sync(0xffffffffu, local, o);
    if ((t & 31) == 0) ws[t >> 5] = local;
    __syncthreads();
    if (t == 0) {
        double tot = 0.0;
#pragma unroll
        for (int w = 0; w < 12; w++) tot += ws[w];
        out[0] = (float)(-0.5 * tot / (double)NB);
    }
}

// ---------------------------------------------------------------------------
extern "C" void kernel_launch(void* const* d_in, const int* in_sizes, int n_in,
                              void* d_out, int out_size) {
    const float* seg = (const float*)d_in[0];
    const void*  lab = d_in[1];
    float* out = (float*)d_out;

    size_t smem = (size_t)NBINS * T * sizeof(float);  // 194,560 B
    (void)cudaFuncSetAttribute(accum_kernel,
                               cudaFuncAttributeMaxDynamicSharedMemorySize, (int)smem);

    detect_kernel<<<1, 1>>>((const int*)lab);
    dim3 grid(GX, NB);
    accum_kernel<<<grid, T, smem>>>(seg, lab);
    finalize_kernel<<<1, 384>>>(out);
}